// round 11
// baseline (speedup 1.0000x reference)
#include <cuda_runtime.h>
#include <cuda_bf16.h>
#include <stdint.h>

constexpr int B    = 4;
constexpr int H    = 8;
constexpr int LQ   = 1024;
constexpr int DH   = 64;
constexpr int KLEN = 1024;
constexpr int TBL  = 33;     // 2*MAX_REL_POS + 1
constexpr int TP   = 68;     // padded row stride (272B): bank-skewed
constexpr int PS   = 34;     // S2 row stride
constexpr int G    = 4;      // qpos per block

__device__ __forceinline__ void ffma2(unsigned long long& acc,
                                      unsigned long long a,
                                      unsigned long long b)
{
    asm("fma.rn.f32x2 %0, %1, %2, %0;" : "+l"(acc) : "l"(a), "l"(b));
}
__device__ __forceinline__ float f2lo(unsigned long long v) {
    return __uint_as_float((unsigned)v);
}
__device__ __forceinline__ float f2hi(unsigned long long v) {
    return __uint_as_float((unsigned)(v >> 32));
}

// ---------------------------------------------------------------------------
// Fused kernel, one block per FOUR consecutive (b,q). Table staged once,
// barriers amortized over 128 KB of stores, time_ids window loaded once.
// S-compute map (per g): h = lane>>2, j = warp*4 + (lane&3):
//   q chunk = 8 rows x 16B @272B stride -> 1 wavefront
//   t chunk = 4 rows x 16B              -> 1 wavefront
// Store phase: per g, warp-uniform idx fast path (sorted ids) else 4 scalar
// LDS per h; 32 coalesced streaming STG.128 per thread per block.
// ---------------------------------------------------------------------------
__global__ __launch_bounds__(256)
void relpe_fused(const float* __restrict__ q,
                 const float* __restrict__ table,
                 const int* __restrict__ tids,
                 float* __restrict__ out)
{
    __shared__ __align__(16) float tsh[TBL * TP];       // 8.8 KB
    __shared__ __align__(16) float qsh[G * H * TP];     // 8.5 KB
    __shared__ float S2[G * H * PS];                    // 4.3 KB

    const int blk = blockIdx.x;          // 0 .. B*LQ/G - 1
    const int b   = blk >> 8;            // 256 blocks per batch
    const int q0  = (blk & 255) * G;     // first qpos of this block
    const int tid = threadIdx.x;

    // ---- stage table: 528 float4 ----
    {
        const float4* t4 = reinterpret_cast<const float4*>(table);
        for (int i = tid; i < (TBL * DH) / 4; i += 256) {
            float4 v = t4[i];
            *reinterpret_cast<float4*>(&tsh[(i >> 4) * TP + 4 * (i & 15)]) = v;
        }
    }
    // ---- stage 4 q slabs: 512 float4 (2 per thread) ----
    for (int i = tid; i < G * H * 16; i += 256) {
        int g  = i >> 7;
        int h  = (i >> 4) & 7;
        int c4 = i & 15;
        float4 v = reinterpret_cast<const float4*>(
            q + (((size_t)b * H + h) * LQ + q0 + g) * DH)[c4];
        *reinterpret_cast<float4*>(&qsh[(g * H + h) * TP + 4 * c4]) = v;
    }

    // ---- time ids: k-window once, tq per g ----
    int4 t4i = reinterpret_cast<const int4*>(tids + (size_t)b * KLEN)[tid];
    int tq0 = tids[b * KLEN + q0];
    int tq1 = tids[b * KLEN + q0 + 1];
    int tq2 = tids[b * KLEN + q0 + 2];
    int tq3 = tids[b * KLEN + q0 + 3];

    __syncthreads();

    // ---- S compute: 4 slabs, map h = lane>>2, j = warp*4 + (lane&3) ----
    {
        const int l  = tid & 31;
        const int w  = tid >> 5;
        const int h  = l >> 2;
        const int jj = w * 4 + (l & 3);     // 0..31
        #pragma unroll
        for (int g = 0; g < G; g++) {
            const ulonglong2* qrow =
                reinterpret_cast<const ulonglong2*>(&qsh[(g * H + h) * TP]);
            const ulonglong2* trow =
                reinterpret_cast<const ulonglong2*>(&tsh[jj * TP]);
            unsigned long long a0 = 0ull, a1 = 0ull;
            #pragma unroll
            for (int c = 0; c < 16; c++) {
                ulonglong2 qa = qrow[c];
                ulonglong2 ta = trow[c];
                ffma2(a0, qa.x, ta.x);
                ffma2(a1, qa.y, ta.y);
            }
            S2[(g * H + h) * PS + jj] =
                (f2lo(a0) + f2hi(a0)) + (f2lo(a1) + f2hi(a1));
        }
        // tail j = 32: threads 0..31 -> (g = tid>>3, h = tid&7)
        if (tid < 32) {
            int g = tid >> 3, h2 = tid & 7;
            const ulonglong2* qr2 =
                reinterpret_cast<const ulonglong2*>(&qsh[(g * H + h2) * TP]);
            const ulonglong2* tr2 =
                reinterpret_cast<const ulonglong2*>(&tsh[32 * TP]);
            unsigned long long b0 = 0ull, b1 = 0ull;
            #pragma unroll
            for (int c = 0; c < 16; c++) {
                ulonglong2 qa = qr2[c];
                ulonglong2 ta = tr2[c];
                ffma2(b0, qa.x, ta.x);
                ffma2(b1, qa.y, ta.y);
            }
            S2[(g * H + h2) * PS + 32] =
                (f2lo(b0) + f2hi(b0)) + (f2lo(b1) + f2hi(b1));
        }
    }
    __syncthreads();

    // ---- gather + stream: 4 qpos x 8 h x STG.128 per thread ----
    const unsigned FULL = 0xffffffffu;
    int tqs[G] = {tq0, tq1, tq2, tq3};
    #pragma unroll
    for (int g = 0; g < G; g++) {
        const int tq = tqs[g];
        int i0 = t4i.x - tq; i0 = i0 < -16 ? -16 : (i0 > 16 ? 16 : i0); i0 += 16;
        int i1 = t4i.y - tq; i1 = i1 < -16 ? -16 : (i1 > 16 ? 16 : i1); i1 += 16;
        int i2 = t4i.z - tq; i2 = i2 < -16 ? -16 : (i2 > 16 ? 16 : i2); i2 += 16;
        int i3 = t4i.w - tq; i3 = i3 < -16 ? -16 : (i3 > 16 ? 16 : i3); i3 += 16;

        const int  ilead = __shfl_sync(FULL, i0, 0);
        const bool uniw  = __all_sync(FULL,
            (i0 == i1) && (i1 == i2) && (i2 == i3) && (i0 == ilead));

        const float* Sg = &S2[g * H * PS];
        if (uniw) {
            #pragma unroll
            for (int h = 0; h < H; h++) {
                float s = Sg[h * PS + ilead];
                float4 v = make_float4(s, s, s, s);
                float4* o4 = reinterpret_cast<float4*>(
                    out + ((((size_t)b * H + h) * LQ + q0 + g) * KLEN));
                __stcs(o4 + tid, v);
            }
        } else {
            #pragma unroll
            for (int h = 0; h < H; h++) {
                const float* row = &Sg[h * PS];
                float4 v;
                v.x = row[i0];
                v.y = row[i1];
                v.z = row[i2];
                v.w = row[i3];
                float4* o4 = reinterpret_cast<float4*>(
                    out + ((((size_t)b * H + h) * LQ + q0 + g) * KLEN));
                __stcs(o4 + tid, v);
            }
        }
    }
}

extern "C" void kernel_launch(void* const* d_in, const int* in_sizes, int n_in,
                              void* d_out, int out_size)
{
    const float* q     = (const float*)d_in[0];
    const float* table = (const float*)d_in[1];
    const int*   tids  = (const int*)d_in[2];
    float*       out   = (float*)d_out;

    relpe_fused<<<(B * LQ) / G, 256>>>(q, table, tids, out);
}